// round 2
// baseline (speedup 1.0000x reference)
#include <cuda_runtime.h>
#include <math.h>
#include <stdint.h>

#define TOKENS 4096
#define HID    4096
#define NEXP   4
#define FDIM   8192
#define OUTD   1792

// ---------------- scratch (device globals; no allocs allowed) ----------------
__device__ __align__(256) float g_H[(size_t)2 * TOKENS * FDIM];   // 256 MB
__device__ __align__(256) float g_Y[(size_t)2 * TOKENS * OUTD];   // 56 MB
__device__ __align__(256) float g_gates[2 * TOKENS];
__device__ __align__(256) int   g_rows[NEXP * TOKENS];
__device__ __align__(256) int   g_cnt[NEXP];

// ---------------- helpers ----------------
__device__ __forceinline__ unsigned f2tf(float x) {
    unsigned r;
    asm("cvt.rna.tf32.f32 %0, %1;" : "=r"(r) : "f"(x));
    return r;
}
__device__ __forceinline__ float4 cvt4(float4 v) {
    float4 o;
    o.x = __uint_as_float(f2tf(v.x));
    o.y = __uint_as_float(f2tf(v.y));
    o.z = __uint_as_float(f2tf(v.z));
    o.w = __uint_as_float(f2tf(v.w));
    return o;
}
__device__ __forceinline__ void mma_tf32(float c[4],
                                         unsigned a0, unsigned a1, unsigned a2, unsigned a3,
                                         unsigned b0, unsigned b1) {
    asm volatile(
        "mma.sync.aligned.m16n8k8.row.col.f32.tf32.tf32.f32 "
        "{%0,%1,%2,%3}, {%4,%5,%6,%7}, {%8,%9}, {%0,%1,%2,%3};\n"
        : "+f"(c[0]), "+f"(c[1]), "+f"(c[2]), "+f"(c[3])
        : "r"(a0), "r"(a1), "r"(a2), "r"(a3), "r"(b0), "r"(b1));
}
__device__ __forceinline__ float gelu_exact(float x) {
    return 0.5f * x * (1.0f + erff(x * 0.70710678118654752440f));
}

// ---------------- init ----------------
__global__ void init_cnt_kernel(int* cnt) {
    if (threadIdx.x < NEXP) cnt[threadIdx.x] = 0;
}

// ---------------- router: 1 warp per token ----------------
__global__ void __launch_bounds__(256) router_kernel(
    const float* __restrict__ hs, const float* __restrict__ rw,
    const float* __restrict__ rb, int* __restrict__ cnt,
    int* __restrict__ rows, float* __restrict__ gates) {
    int warp = threadIdx.x >> 5;
    int lane = threadIdx.x & 31;
    int t = blockIdx.x * 8 + warp;
    if (t >= TOKENS) return;

    float a0 = 0.f, a1 = 0.f, a2 = 0.f, a3 = 0.f;
    const float4* x = (const float4*)(hs + (size_t)t * HID);
    const float4* w = (const float4*)rw;  // [HID][4] rows, each row is one float4
    #pragma unroll 4
    for (int i = lane; i < HID / 4; i += 32) {
        float4 v = x[i];
        float4 w0 = w[4 * i + 0];
        float4 w1 = w[4 * i + 1];
        float4 w2 = w[4 * i + 2];
        float4 w3 = w[4 * i + 3];
        a0 += v.x * w0.x + v.y * w1.x + v.z * w2.x + v.w * w3.x;
        a1 += v.x * w0.y + v.y * w1.y + v.z * w2.y + v.w * w3.y;
        a2 += v.x * w0.z + v.y * w1.z + v.z * w2.z + v.w * w3.z;
        a3 += v.x * w0.w + v.y * w1.w + v.z * w2.w + v.w * w3.w;
    }
    #pragma unroll
    for (int s = 16; s > 0; s >>= 1) {
        a0 += __shfl_xor_sync(0xffffffffu, a0, s);
        a1 += __shfl_xor_sync(0xffffffffu, a1, s);
        a2 += __shfl_xor_sync(0xffffffffu, a2, s);
        a3 += __shfl_xor_sync(0xffffffffu, a3, s);
    }
    if (lane == 0) {
        float l[NEXP] = {a0 + rb[0], a1 + rb[1], a2 + rb[2], a3 + rb[3]};
        int i0 = 0;
        #pragma unroll
        for (int e = 1; e < NEXP; e++)
            if (l[e] > l[i0]) i0 = e;
        int i1 = -1;
        #pragma unroll
        for (int e = 0; e < NEXP; e++) {
            if (e == i0) continue;
            if (i1 < 0 || l[e] > l[i1]) i1 = e;
        }
        float q = expf(l[i1] - l[i0]);  // <= 1
        float g0 = 1.0f / (1.0f + q);
        float g1 = q / (1.0f + q);
        int p0 = atomicAdd(&cnt[i0], 1);
        rows[i0 * TOKENS + p0] = 2 * t;
        int p1 = atomicAdd(&cnt[i1], 1);
        rows[i1 * TOKENS + p1] = 2 * t + 1;
        gates[2 * t] = g0;
        gates[2 * t + 1] = g1;
    }
}

// ---------------- expert GEMM (tf32 mma.sync) ----------------
// CTA tile 128x256, BK=16, 8 warps (2x4), warp tile 64x64.
// A gathered rows via rows_list; GATHER_SHIFT: row index = gr>>1 (hidden) else gr (H).
#define BM 128
#define BN 256
#define BKK 16
#define ASTR 20   // BKK + 4 pad (conflict-free frag reads, pattern (20g+t)%32 distinct)
#define BSTR 264  // BN + 8 pad  (pattern (8t+g)%32 distinct)
#define SMEM_BYTES (size_t)(2 * (BM * ASTR + BKK * BSTR) * 4)

template <bool GATHER_SHIFT, bool DO_GELU>
__global__ void __launch_bounds__(256, 1) gemm_moe_kernel(
    const float* __restrict__ Abase, const float* __restrict__ W,
    const float* __restrict__ bias, float* __restrict__ Out,
    const int* __restrict__ rows_list, const int* __restrict__ cnt,
    int N, int K) {
    const int e = blockIdx.z;
    const int m0 = blockIdx.y * BM;
    const int n0 = blockIdx.x * BN;
    const int cn = cnt[e];
    if (m0 >= cn) return;

    extern __shared__ float sm[];
    float* As = sm;                      // [2][BM][ASTR]
    float* Bs = sm + 2 * BM * ASTR;      // [2][BKK][BSTR]
    const int ASZ = BM * ASTR;
    const int BSZ = BKK * BSTR;

    const int tid = threadIdx.x;
    const int lane = tid & 31;
    const int warp = tid >> 5;
    const int g = lane >> 2;
    const int t = lane & 3;
    const int wm = warp >> 2;  // 0..1
    const int wn = warp & 3;   // 0..3

    const float* Wp = W + (size_t)e * K * N + n0;

    // A staging address bases (2 float4 per thread)
    size_t aoff[2];
    int arow[2], aq[2];
    #pragma unroll
    for (int n = 0; n < 2; n++) {
        int L = tid + n * 256;
        arow[n] = L >> 2;
        aq[n] = L & 3;
        int gr = rows_list[e * TOKENS + m0 + arow[n]];  // safe even past cnt
        int ridx = GATHER_SHIFT ? (gr >> 1) : gr;
        aoff[n] = (size_t)ridx * K + aq[n] * 4;
    }
    // B staging coords (4 float4 per thread)
    int bk[4], bnq[4];
    #pragma unroll
    for (int n = 0; n < 4; n++) {
        int L = tid + n * 256;
        bk[n] = L >> 6;
        bnq[n] = L & 63;
    }

    float c[4][8][4];
    #pragma unroll
    for (int mi = 0; mi < 4; mi++)
        #pragma unroll
        for (int ni = 0; ni < 8; ni++)
            #pragma unroll
            for (int r = 0; r < 4; r++) c[mi][ni][r] = 0.f;

    const int KT = K / BKK;
    float4 ra[2], rb[4];

    // prologue: tile 0
    #pragma unroll
    for (int n = 0; n < 2; n++) ra[n] = *(const float4*)(Abase + aoff[n]);
    #pragma unroll
    for (int n = 0; n < 4; n++)
        rb[n] = *(const float4*)(Wp + (size_t)bk[n] * N + bnq[n] * 4);
    #pragma unroll
    for (int n = 0; n < 2; n++)
        *(float4*)&As[arow[n] * ASTR + aq[n] * 4] = cvt4(ra[n]);
    #pragma unroll
    for (int n = 0; n < 4; n++)
        *(float4*)&Bs[bk[n] * BSTR + bnq[n] * 4] = cvt4(rb[n]);
    __syncthreads();

    for (int kt = 0; kt < KT; kt++) {
        if (kt + 1 < KT) {
            int kbase = (kt + 1) * BKK;
            #pragma unroll
            for (int n = 0; n < 2; n++)
                ra[n] = *(const float4*)(Abase + aoff[n] + kbase);
            #pragma unroll
            for (int n = 0; n < 4; n++)
                rb[n] = *(const float4*)(Wp + (size_t)(kbase + bk[n]) * N + bnq[n] * 4);
        }
        const float* A_ = As + (kt & 1) * ASZ;
        const float* B_ = Bs + (kt & 1) * BSZ;
        #pragma unroll
        for (int ks = 0; ks < 2; ks++) {
            const int kk = ks * 8;
            unsigned a[4][4];
            #pragma unroll
            for (int mi = 0; mi < 4; mi++) {
                int mb = wm * 64 + mi * 16;
                a[mi][0] = __float_as_uint(A_[(mb + g) * ASTR + kk + t]);
                a[mi][1] = __float_as_uint(A_[(mb + g + 8) * ASTR + kk + t]);
                a[mi][2] = __float_as_uint(A_[(mb + g) * ASTR + kk + t + 4]);
                a[mi][3] = __float_as_uint(A_[(mb + g + 8) * ASTR + kk + t + 4]);
            }
            #pragma unroll
            for (int ni = 0; ni < 8; ni++) {
                int nb = wn * 64 + ni * 8;
                unsigned b0 = __float_as_uint(B_[(kk + t) * BSTR + nb + g]);
                unsigned b1 = __float_as_uint(B_[(kk + t + 4) * BSTR + nb + g]);
                #pragma unroll
                for (int mi = 0; mi < 4; mi++)
                    mma_tf32(c[mi][ni], a[mi][0], a[mi][1], a[mi][2], a[mi][3], b0, b1);
            }
        }
        if (kt + 1 < KT) {
            float* An = As + ((kt + 1) & 1) * ASZ;
            float* Bn = Bs + ((kt + 1) & 1) * BSZ;
            #pragma unroll
            for (int n = 0; n < 2; n++)
                *(float4*)&An[arow[n] * ASTR + aq[n] * 4] = cvt4(ra[n]);
            #pragma unroll
            for (int n = 0; n < 4; n++)
                *(float4*)&Bn[bk[n] * BSTR + bnq[n] * 4] = cvt4(rb[n]);
        }
        __syncthreads();
    }

    // epilogue
    int grs[8];
    bool val[8];
    #pragma unroll
    for (int mi = 0; mi < 4; mi++) {
        int r0 = m0 + wm * 64 + mi * 16 + g;
        int r1 = r0 + 8;
        val[2 * mi] = (r0 - m0) + m0 < cn && r0 < cn;
        val[2 * mi + 1] = r1 < cn;
        grs[2 * mi] = rows_list[e * TOKENS + r0];
        grs[2 * mi + 1] = rows_list[e * TOKENS + r1];
    }
    #pragma unroll
    for (int mi = 0; mi < 4; mi++) {
        #pragma unroll
        for (int ni = 0; ni < 8; ni++) {
            int col = n0 + wn * 64 + ni * 8 + 2 * t;
            float2 bv = *(const float2*)(bias + (size_t)e * N + col);
            float x0 = c[mi][ni][0] + bv.x;
            float x1 = c[mi][ni][1] + bv.y;
            float x2 = c[mi][ni][2] + bv.x;
            float x3 = c[mi][ni][3] + bv.y;
            if (DO_GELU) {
                x0 = gelu_exact(x0);
                x1 = gelu_exact(x1);
                x2 = gelu_exact(x2);
                x3 = gelu_exact(x3);
            }
            if (val[2 * mi]) {
                float2 v = make_float2(x0, x1);
                *(float2*)(Out + (size_t)grs[2 * mi] * N + col) = v;
            }
            if (val[2 * mi + 1]) {
                float2 v = make_float2(x2, x3);
                *(float2*)(Out + (size_t)grs[2 * mi + 1] * N + col) = v;
            }
        }
    }
}

// ---------------- combine: out[t] = g0*Y[2t] + g1*Y[2t+1] ----------------
__global__ void __launch_bounds__(256) combine_kernel(
    const float* __restrict__ Y, const float* __restrict__ gates,
    float* __restrict__ out) {
    int idx = blockIdx.x * blockDim.x + threadIdx.x;
    const int JW = OUTD / 4;  // 448
    if (idx >= TOKENS * JW) return;
    int t = idx / JW;
    int j = idx - t * JW;
    float g0 = gates[2 * t];
    float g1 = gates[2 * t + 1];
    float4 y0 = ((const float4*)(Y + (size_t)(2 * t) * OUTD))[j];
    float4 y1 = ((const float4*)(Y + (size_t)(2 * t + 1) * OUTD))[j];
    float4 o;
    o.x = g0 * y0.x + g1 * y1.x;
    o.y = g0 * y0.y + g1 * y1.y;
    o.z = g0 * y0.z + g1 * y1.z;
    o.w = g0 * y0.w + g1 * y1.w;
    ((float4*)(out + (size_t)t * OUTD))[j] = o;
}

// ---------------- launch ----------------
extern "C" void kernel_launch(void* const* d_in, const int* in_sizes, int n_in,
                              void* d_out, int out_size) {
    const float* hs = (const float*)d_in[0];
    const float* rw = (const float*)d_in[1];
    const float* rb = (const float*)d_in[2];
    const float* w1 = (const float*)d_in[3];
    const float* b1 = (const float*)d_in[4];
    const float* w2 = (const float*)d_in[5];
    const float* b2 = (const float*)d_in[6];
    float* out = (float*)d_out;

    float *H, *Y, *gates;
    int *cnt, *rows;
    cudaGetSymbolAddress((void**)&H, g_H);
    cudaGetSymbolAddress((void**)&Y, g_Y);
    cudaGetSymbolAddress((void**)&gates, g_gates);
    cudaGetSymbolAddress((void**)&cnt, g_cnt);
    cudaGetSymbolAddress((void**)&rows, g_rows);

    cudaFuncSetAttribute((const void*)gemm_moe_kernel<true, true>,
                         cudaFuncAttributeMaxDynamicSharedMemorySize, (int)SMEM_BYTES);
    cudaFuncSetAttribute((const void*)gemm_moe_kernel<false, false>,
                         cudaFuncAttributeMaxDynamicSharedMemorySize, (int)SMEM_BYTES);

    init_cnt_kernel<<<1, 32>>>(cnt);
    router_kernel<<<TOKENS / 8, 256>>>(hs, rw, rb, cnt, rows, gates);

    // GEMM1: hidden (gathered, row=gr>>1) x w1 -> GELU -> H   [N=FDIM, K=HID]
    gemm_moe_kernel<true, true><<<dim3(FDIM / BN, TOKENS / BM, NEXP), 256, SMEM_BYTES>>>(
        hs, w1, b1, H, rows, cnt, FDIM, HID);

    // GEMM2: H (row=gr) x w2 -> Y (+b2)   [N=OUTD, K=FDIM]
    gemm_moe_kernel<false, false><<<dim3(OUTD / BN, TOKENS / BM, NEXP), 256, SMEM_BYTES>>>(
        H, w2, b2, Y, rows, cnt, OUTD, FDIM);

    combine_kernel<<<(TOKENS * (OUTD / 4) + 255) / 256, 256>>>(Y, gates, out);
}